// round 13
// baseline (speedup 1.0000x reference)
#include <cuda_runtime.h>

#define NN 4096
#define TT 3
#define DD 20
#define EE 131072      // 2^17
#define ATT_DIM 128
#define HEADS 2
#define LAYERS 2
#define WPR 128        // 32-bit words per bitmap row (4096/32)
#define NEG 0.2f
#define MAXDEG 384     // mean degree ~191; max-degree ~254 across rows
#define L2E 1.4426950408889634f

#define SCAT_BLKS 768            // 768*1024 = 786432 directed half-edges
#define SCORE_BLKS 128           // 128*32 warps = 4096 rows
#define WORKERS (SCAT_BLKS + SCORE_BLKS)   // 896
#define PASS_BLKS 128            // 32 rows/block
#define FUSED_GRID (WORKERS + PASS_BLKS)   // 1024

// ---- device scratch (static, allocation-free) ----
// 3 separate bitmaps (6MB). Start zeroed (.bss); k_pass1 re-zeroes them after
// each replay's use -> invariant holds across graph replays.
__device__ __align__(16) unsigned g_bm[TT][NN * WPR];          // 6MB
__device__ __align__(16) unsigned short g_ent[NN * MAXDEG];    // j | (m<<12)
__device__ int    g_cnt[NN];                                   // even (padded)
__device__ __align__(16) float g_s0[NN];
__device__ __align__(16) float g_s1[NN];
__device__ unsigned g_done = 0;    // worker-blocks retired
__device__ unsigned g_fin  = 0;    // pass-role blocks past the wait

__device__ __forceinline__ float ex2f(float x) {
    float r;
    asm("ex2.approx.ftz.f32 %0, %1;" : "=f"(r) : "f"(x));
    return r;
}
__device__ __forceinline__ void red_or(unsigned* p, unsigned v) {
    asm volatile("red.global.or.b32 [%0], %1;" :: "l"(p), "r"(v) : "memory");
}
__device__ __forceinline__ unsigned ld_acq(const unsigned* p) {
    unsigned v;
    asm volatile("ld.acquire.gpu.u32 %0, [%1];" : "=r"(v) : "l"(p) : "memory");
    return v;
}

// per-layer constants from raw inputs. tabf: [m][4]=(lut_h0',lut_h1',M,_)
__device__ __forceinline__ void compute_consts(int layer, int tid,
                                               const float* __restrict__ edge_emb,
                                               const float* __restrict__ att_w,
                                               float* tabf, float* ab) {
    if (tid < HEADS) {
        int h = tid;
        const float* w = att_w + (layer * HEADS + h) * (DD + 2);
        float et[TT];
        #pragma unroll
        for (int t = 0; t < TT; t++) {
            float acc = 0.0f;
            #pragma unroll
            for (int d = 0; d < DD; d++) acc += edge_emb[t * DD + d] * w[1 + d];
            et[t] = acc * L2E;
        }
        ab[h * 2 + 0] = w[0] * L2E;
        ab[h * 2 + 1] = w[DD + 1] * L2E;
        #pragma unroll
        for (int m = 0; m < 8; m++) {
            float B = 0.0f;
            #pragma unroll
            for (int t = 0; t < TT; t++) if ((m >> t) & 1) B += et[t];
            tabf[m * 4 + h] = B;
        }
    } else if (tid == 2) {
        #pragma unroll
        for (int m = 0; m < 8; m++) tabf[m * 4 + 2] = (float)__popc((unsigned)m);
    }
}

// ============ fused: scatter + scores (workers) + CSR build/layer0 (pass role)
// 1024 blocks x 1024 threads. Pass-role blocks have the HIGHEST blockIdx, so
// they become resident only near the scatter tail (no displacement).
__global__ void __launch_bounds__(1024) k_fused(const int* __restrict__ el,
                                                const float* __restrict__ inputs,
                                                const float* __restrict__ lw,
                                                const float* __restrict__ lb,
                                                const float* __restrict__ edge_emb,
                                                const float* __restrict__ att_w) {
    __shared__ float  ss[NN];                                // 16KB scores
    __shared__ __align__(16) unsigned short se[32][MAXDEG];  // 24KB CSR rows
    __shared__ float4 tab[8];
    __shared__ float  ab[4];
    __shared__ float  red[32];
    __shared__ float  shS;

    int bid = blockIdx.x, tid = threadIdx.x;
    int warp = tid >> 5, lane = tid & 31;

    if (bid < SCAT_BLKS) {
        // ---- scatter: one DIRECTED half-edge per thread
        int i   = bid * 1024 + tid;        // i < 2*TT*EE
        int dir = i & 1;
        int eid = i >> 1;                  // eid < TT*EE
        int t   = eid >> 17;               // EE = 2^17
        int e   = eid & (EE - 1);
        int s = el[(t * 2 + 0) * EE + e];
        int g = el[(t * 2 + 1) * EE + e];
        int from = dir ? g : s;
        int to   = dir ? s : g;
        red_or(&g_bm[t][from * WPR + (to >> 5)], 1u << (to & 31));
        __threadfence();                   // release REDs
        __syncthreads();
        if (tid == 0) atomicAdd(&g_done, 1u);
        return;
    }
    if (bid < WORKERS) {
        // ---- initial linear scores: one row per warp, 32 warps
        int row = (bid - SCAT_BLKS) * 32 + warp;
        float4 v = reinterpret_cast<const float4*>(inputs + row * ATT_DIM)[lane];
        float4 w = reinterpret_cast<const float4*>(lw)[lane];
        float acc = v.x * w.x + v.y * w.y + v.z * w.z + v.w * w.w;
        #pragma unroll
        for (int o = 16; o; o >>= 1) acc += __shfl_xor_sync(0xFFFFFFFFu, acc, o);
        if (lane == 0) g_s0[row] = acc + lb[0];
        __threadfence();                   // release score stores
        __syncthreads();
        if (tid == 0) atomicAdd(&g_done, 1u);
        return;
    }

    // ================= pass role: CSR build + layer-0 attention =================
    int row = (bid - WORKERS) * 32 + warp;

    // constants from raw inputs (safe before the wait)
    compute_consts(0, tid, edge_emb, att_w, reinterpret_cast<float*>(tab), ab);

    // wait for all worker blocks (acquire), then self-reset counters
    if (tid == 0) {
        while (ld_acq(&g_done) < (unsigned)WORKERS) __nanosleep(64);
        if (atomicAdd(&g_fin, 1u) == (unsigned)(PASS_BLKS - 1)) {
            atomicExch(&g_done, 0u);       // all pass blocks past the poll
            atomicExch(&g_fin, 0u);
        }
    }
    __syncthreads();

    // ---- stage scores + S partials
    float4 sv = __ldcg(reinterpret_cast<const float4*>(g_s0) + tid);
    reinterpret_cast<float4*>(ss)[tid] = sv;
    float part = (sv.x + sv.y) + (sv.z + sv.w);
    #pragma unroll
    for (int o = 16; o; o >>= 1) part += __shfl_xor_sync(0xFFFFFFFFu, part, o);
    if (lane == 0) red[warp] = part;

    // ---- bitmap read (uint4 per type); zeroing deferred to k_pass1
    uint4 a0 = __ldcg(reinterpret_cast<const uint4*>(&g_bm[0][0]) + row * 32 + lane);
    uint4 a1 = __ldcg(reinterpret_cast<const uint4*>(&g_bm[1][0]) + row * 32 + lane);
    uint4 a2 = __ldcg(reinterpret_cast<const uint4*>(&g_bm[2][0]) + row * 32 + lane);

    // ---- per-lane counts + warp scan
    unsigned u0 = a0.x | a1.x | a2.x;
    unsigned u1 = a0.y | a1.y | a2.y;
    unsigned u2 = a0.z | a1.z | a2.z;
    unsigned u3 = a0.w | a1.w | a2.w;
    int cnt = __popc(u0) + __popc(u1) + __popc(u2) + __popc(u3);

    int inc = cnt;
    #pragma unroll
    for (int o = 1; o < 32; o <<= 1) {
        int n = __shfl_up_sync(0xFFFFFFFFu, inc, o);
        if (lane >= o) inc += n;
    }
    int base = inc - cnt;
    int tot  = __shfl_sync(0xFFFFFFFFu, inc, 31);

    // ---- extract into this warp's smem CSR row
    unsigned short* sw = &se[warp][0];
    #pragma unroll
    for (int c = 0; c < 4; c++) {
        unsigned u  = (c == 0) ? u0   : (c == 1) ? u1   : (c == 2) ? u2   : u3;
        unsigned w0 = (c == 0) ? a0.x : (c == 1) ? a0.y : (c == 2) ? a0.z : a0.w;
        unsigned w1 = (c == 0) ? a1.x : (c == 1) ? a1.y : (c == 2) ? a1.z : a1.w;
        unsigned w2 = (c == 0) ? a2.x : (c == 1) ? a2.y : (c == 2) ? a2.z : a2.w;
        int col = (lane * 4 + c) * 32;
        while (u) {
            int b = __ffs(u) - 1;
            u &= u - 1;
            int m = ((w0 >> b) & 1) | (((w1 >> b) & 1) << 1) | (((w2 >> b) & 1) << 2);
            sw[base++] = (unsigned short)((col + b) | (m << 12));
        }
    }
    if (lane == 31 && (tot & 1)) sw[tot] = 0;     // pad entry (exact no-op)
    int cpad = (tot + 1) & ~1;
    if (lane == 0) g_cnt[row] = cpad;
    __syncwarp();

    // ---- stream used entries to gmem for layer 1 (predicated uint4)
    {
        int nv4 = (cpad + 7) >> 3;                // uint4 vectors in use
        uint4* go = reinterpret_cast<uint4*>(&g_ent[row * MAXDEG]);
        const uint4* so = reinterpret_cast<const uint4*>(sw);
        if (lane < nv4)      go[lane]      = so[lane];
        if (lane + 32 < nv4) go[lane + 32] = so[lane + 32];
    }

    __syncthreads();                               // ss + red ready
    if (tid < 32) {
        float v = red[tid];
        #pragma unroll
        for (int o = 16; o; o >>= 1) v += __shfl_xor_sync(0xFFFFFFFFu, v, o);
        if (tid == 0) shS = v;
    }
    __syncthreads();

    // ---- layer-0 attention, entries from smem
    float S  = shS;
    float si = ss[row];
    float a0f = ab[0], b0f = ab[1], a1f = ab[2], b1f = ab[3];
    float c0 = a0f * si, c1 = a1f * si;

    const unsigned* ep32 = reinterpret_cast<const unsigned*>(sw);
    int nit = cpad >> 1;
    float e0 = 0.0f, n0 = 0.0f, e1 = 0.0f, n1 = 0.0f, sjs = 0.0f;

    for (int k = lane; k < nit; k += 32) {
        unsigned pr = ep32[k];
        #pragma unroll
        for (int half = 0; half < 2; half++) {
            int e = (half == 0) ? (pr & 0xFFFFu) : (pr >> 16);
            int j = e & 0xFFF;
            int m = e >> 12;
            float4 t4 = tab[m];           // (lut0', lut1', M, _)
            float sj = ss[j];
            float M  = t4.z;

            float x0 = fmaf(M, fmaf(b0f, sj, c0), t4.x);
            x0 = fmaxf(x0, NEG * x0);     // lrelu commutes with log2e scale
            float v0 = ex2f(x0);
            e0 += v0; n0 = fmaf(v0, sj, n0);

            float x1 = fmaf(M, fmaf(b1f, sj, c1), t4.y);
            x1 = fmaxf(x1, NEG * x1);
            float v1 = ex2f(x1);
            e1 += v1; n1 = fmaf(v1, sj, n1);

            sjs += sj;
        }
    }

    #pragma unroll
    for (int o = 16; o; o >>= 1) {
        e0  += __shfl_xor_sync(0xFFFFFFFFu, e0,  o);
        n0  += __shfl_xor_sync(0xFFFFFFFFu, n0,  o);
        e1  += __shfl_xor_sync(0xFFFFFFFFu, e1,  o);
        n1  += __shfl_xor_sync(0xFFFFFFFFu, n1,  o);
        sjs += __shfl_xor_sync(0xFFFFFFFFu, sjs, o);
    }
    if (lane == 0) {
        float fc = (float)cpad;
        float r0 = (S + n0 - sjs) / ((float)NN + e0 - fc);
        float r1 = (S + n1 - sjs) / ((float)NN + e1 - fc);
        g_s1[row] = 0.5f * (r0 + r1);
    }
}

// ---------------- layer-1 attention (entries L2-warm) + bitmap zero-restore
__global__ void __launch_bounds__(1024) k_pass1(const float* __restrict__ edge_emb,
                                                const float* __restrict__ att_w,
                                                float* __restrict__ out) {
    __shared__ float  ss[NN];
    __shared__ float4 tab[8];
    __shared__ float  ab[4];
    __shared__ float  red[32];
    __shared__ float  shS;

    int tid = threadIdx.x, warp = tid >> 5, lane = tid & 31;
    int row = blockIdx.x * 32 + warp;

    int cnt = g_cnt[row];
    const unsigned* __restrict__ ep32 =
        reinterpret_cast<const unsigned*>(&g_ent[row * MAXDEG]);
    unsigned pr[6];
    #pragma unroll
    for (int q = 0; q < 6; q++) pr[q] = ep32[lane + q * 32];   // MLP=6

    // zero-restore this row's bitmap words for the next replay
    {
        uint4 z = make_uint4(0u, 0u, 0u, 0u);
        reinterpret_cast<uint4*>(&g_bm[0][0])[row * 32 + lane] = z;
        reinterpret_cast<uint4*>(&g_bm[1][0])[row * 32 + lane] = z;
        reinterpret_cast<uint4*>(&g_bm[2][0])[row * 32 + lane] = z;
    }

    float4 sv = __ldcg(reinterpret_cast<const float4*>(g_s1) + tid);
    reinterpret_cast<float4*>(ss)[tid] = sv;
    float part = (sv.x + sv.y) + (sv.z + sv.w);
    #pragma unroll
    for (int o = 16; o; o >>= 1) part += __shfl_xor_sync(0xFFFFFFFFu, part, o);
    if (lane == 0) red[warp] = part;
    compute_consts(1, tid, edge_emb, att_w, reinterpret_cast<float*>(tab), ab);
    __syncthreads();

    if (tid < 32) {
        float v = red[tid];
        #pragma unroll
        for (int o = 16; o; o >>= 1) v += __shfl_xor_sync(0xFFFFFFFFu, v, o);
        if (tid == 0) shS = v;
    }
    __syncthreads();

    float S  = shS;
    float si = ss[row];
    float a0f = ab[0], b0f = ab[1], a1f = ab[2], b1f = ab[3];
    float c0 = a0f * si, c1 = a1f * si;

    int nit = cnt >> 1;
    float e0 = 0.0f, n0 = 0.0f, e1 = 0.0f, n1 = 0.0f, sjs = 0.0f;

    #pragma unroll
    for (int q = 0; q < 6; q++) {
        if (lane + q * 32 < nit) {
            unsigned prq = pr[q];
            #pragma unroll
            for (int half = 0; half < 2; half++) {
                int e = (half == 0) ? (prq & 0xFFFFu) : (prq >> 16);
                int j = e & 0xFFF;
                int m = e >> 12;
                float4 t4 = tab[m];
                float sj = ss[j];
                float M  = t4.z;

                float x0 = fmaf(M, fmaf(b0f, sj, c0), t4.x);
                x0 = fmaxf(x0, NEG * x0);
                float v0 = ex2f(x0);
                e0 += v0; n0 = fmaf(v0, sj, n0);

                float x1 = fmaf(M, fmaf(b1f, sj, c1), t4.y);
                x1 = fmaxf(x1, NEG * x1);
                float v1 = ex2f(x1);
                e1 += v1; n1 = fmaf(v1, sj, n1);

                sjs += sj;
            }
        }
    }

    #pragma unroll
    for (int o = 16; o; o >>= 1) {
        e0  += __shfl_xor_sync(0xFFFFFFFFu, e0,  o);
        n0  += __shfl_xor_sync(0xFFFFFFFFu, n0,  o);
        e1  += __shfl_xor_sync(0xFFFFFFFFu, e1,  o);
        n1  += __shfl_xor_sync(0xFFFFFFFFu, n1,  o);
        sjs += __shfl_xor_sync(0xFFFFFFFFu, sjs, o);
    }
    if (lane == 0) {
        float fc = (float)cnt;
        float r0 = (S + n0 - sjs) / ((float)NN + e0 - fc);
        float r1 = (S + n1 - sjs) / ((float)NN + e1 - fc);
        out[row] = 0.5f * (r0 + r1);
    }
}

// ---------------------------------------------------------------- launch
extern "C" void kernel_launch(void* const* d_in, const int* in_sizes, int n_in,
                              void* d_out, int out_size) {
    const float* inputs     = (const float*)d_in[0];
    const float* lin_w      = (const float*)d_in[1];
    const float* lin_b      = (const float*)d_in[2];
    const float* edge_emb   = (const float*)d_in[3];
    const float* att_w      = (const float*)d_in[4];
    const int*   edge_lists = (const int*)  d_in[5];
    float* out = (float*)d_out;

    k_fused<<<FUSED_GRID, 1024>>>(edge_lists, inputs, lin_w, lin_b, edge_emb, att_w);
    k_pass1<<<PASS_BLKS, 1024>>>(edge_emb, att_w, out);
}

// round 14
// speedup vs baseline: 1.3631x; 1.3631x over previous
#include <cuda_runtime.h>

#define NN 4096
#define TT 3
#define DD 20
#define EE 131072      // 2^17
#define ATT_DIM 128
#define HEADS 2
#define LAYERS 2
#define WPR 128        // 32-bit words per bitmap row (4096/32)
#define NEG 0.2f
#define MAXDEG 384     // mean degree ~191; max-degree ~254 across rows
#define L2E 1.4426950408889634f

#define SCAT_BLKS (TT * EE * 2 / 256)          // 3072: one directed half-edge/thread
#define SCORE_BLKS 512                         // 4096 rows / 8 warps
#define PREP_BLKS (SCAT_BLKS + SCORE_BLKS)
#define PASS_BLKS 128                          // 32 rows/block, single wave

// ---- device scratch (static, allocation-free) ----
// 3 separate bitmaps (6MB). Start zeroed (.bss); k_pass0 re-zeroes after
// reading -> invariant holds across graph replays.
__device__ __align__(16) unsigned g_bm[TT][NN * WPR];          // 6MB
__device__ __align__(16) unsigned short g_ent[NN * MAXDEG];    // j | (m<<12)
__device__ int    g_cnt[NN];                                   // even (padded)
__device__ __align__(16) float g_s0[NN];
__device__ __align__(16) float g_s1[NN];

__device__ __forceinline__ float ex2f(float x) {
    float r;
    asm("ex2.approx.ftz.f32 %0, %1;" : "=f"(r) : "f"(x));
    return r;
}
__device__ __forceinline__ void red_or(unsigned* p, unsigned v) {
    asm volatile("red.global.or.b32 [%0], %1;" :: "l"(p), "r"(v) : "memory");
}

// per-layer constants from raw inputs. tabf: [m][4]=(lut_h0',lut_h1',M,_)
__device__ __forceinline__ void compute_consts(int layer, int tid,
                                               const float* __restrict__ edge_emb,
                                               const float* __restrict__ att_w,
                                               float* tabf, float* ab) {
    if (tid < HEADS) {
        int h = tid;
        const float* w = att_w + (layer * HEADS + h) * (DD + 2);
        float et[TT];
        #pragma unroll
        for (int t = 0; t < TT; t++) {
            float acc = 0.0f;
            #pragma unroll
            for (int d = 0; d < DD; d++) acc += edge_emb[t * DD + d] * w[1 + d];
            et[t] = acc * L2E;
        }
        ab[h * 2 + 0] = w[0] * L2E;
        ab[h * 2 + 1] = w[DD + 1] * L2E;
        #pragma unroll
        for (int m = 0; m < 8; m++) {
            float B = 0.0f;
            #pragma unroll
            for (int t = 0; t < TT; t++) if ((m >> t) & 1) B += et[t];
            tabf[m * 4 + h] = B;
        }
    } else if (tid == 2) {
        #pragma unroll
        for (int m = 0; m < 8; m++) tabf[m * 4 + 2] = (float)__popc((unsigned)m);
    }
}

// ----------------------- fused: edge scatter + initial scores
__global__ void __launch_bounds__(256) k_prep(const int* __restrict__ el,
                                              const float* __restrict__ inputs,
                                              const float* __restrict__ lw,
                                              const float* __restrict__ lb) {
    int bid = blockIdx.x, tid = threadIdx.x;

    if (bid < SCAT_BLKS) {
        // ---- edge scatter: one DIRECTED half-edge per thread (max concurrency)
        int i   = bid * 256 + tid;         // i < 2*TT*EE
        int dir = i & 1;
        int eid = i >> 1;                  // eid < TT*EE
        int t   = eid >> 17;               // EE = 2^17
        int e   = eid & (EE - 1);
        int s = el[(t * 2 + 0) * EE + e];
        int g = el[(t * 2 + 1) * EE + e];
        int from = dir ? g : s;
        int to   = dir ? s : g;
        red_or(&g_bm[t][from * WPR + (to >> 5)], 1u << (to & 31));
    } else {
        // ---- initial linear scores: one row per warp, 8 warps
        int warp = tid >> 5, lane = tid & 31;
        int row  = (bid - SCAT_BLKS) * 8 + warp;
        float4 v = reinterpret_cast<const float4*>(inputs + row * ATT_DIM)[lane];
        float4 w = reinterpret_cast<const float4*>(lw)[lane];
        float acc = v.x * w.x + v.y * w.y + v.z * w.z + v.w * w.w;
        #pragma unroll
        for (int o = 16; o; o >>= 1) acc += __shfl_xor_sync(0xFFFFFFFFu, acc, o);
        if (lane == 0) g_s0[row] = acc + lb[0];
    }
}

// ---------------- fused: CSR build (own 32 rows) + attention layer 0
// 128 blocks x 1024 threads; warp w owns row blk*32+w; lane owns 4 words/type.
__global__ void __launch_bounds__(1024) k_pass0(const float* __restrict__ edge_emb,
                                                const float* __restrict__ att_w) {
    __shared__ float  ss[NN];                                // 16KB scores
    __shared__ __align__(16) unsigned short se[32][MAXDEG];  // 24KB CSR rows
    __shared__ float4 tab[8];
    __shared__ float  ab[4];
    __shared__ float  red[32];
    __shared__ float  shS;

    int tid = threadIdx.x, warp = tid >> 5, lane = tid & 31;
    int row = blockIdx.x * 32 + warp;

    // ---- A: read this row's bitmap words (uint4 per type), zero-restore
    uint4* b0p = reinterpret_cast<uint4*>(&g_bm[0][0]) + row * 32 + lane;
    uint4* b1p = reinterpret_cast<uint4*>(&g_bm[1][0]) + row * 32 + lane;
    uint4* b2p = reinterpret_cast<uint4*>(&g_bm[2][0]) + row * 32 + lane;
    uint4 a0 = *b0p, a1 = *b1p, a2 = *b2p;

    // ---- B: stage scores + S partials + constants (overlaps bitmap waits)
    float4 sv = __ldcg(reinterpret_cast<const float4*>(g_s0) + tid);
    reinterpret_cast<float4*>(ss)[tid] = sv;
    float part = (sv.x + sv.y) + (sv.z + sv.w);
    #pragma unroll
    for (int o = 16; o; o >>= 1) part += __shfl_xor_sync(0xFFFFFFFFu, part, o);
    if (lane == 0) red[warp] = part;
    compute_consts(0, tid, edge_emb, att_w, reinterpret_cast<float*>(tab), ab);

    uint4 z = make_uint4(0u, 0u, 0u, 0u);
    *b0p = z; *b1p = z; *b2p = z;                 // restore zero invariant

    // ---- C: per-lane counts + warp scan
    unsigned u0 = a0.x | a1.x | a2.x;
    unsigned u1 = a0.y | a1.y | a2.y;
    unsigned u2 = a0.z | a1.z | a2.z;
    unsigned u3 = a0.w | a1.w | a2.w;
    int cnt = __popc(u0) + __popc(u1) + __popc(u2) + __popc(u3);

    int inc = cnt;
    #pragma unroll
    for (int o = 1; o < 32; o <<= 1) {
        int n = __shfl_up_sync(0xFFFFFFFFu, inc, o);
        if (lane >= o) inc += n;
    }
    int base = inc - cnt;
    int tot  = __shfl_sync(0xFFFFFFFFu, inc, 31);

    // ---- D: extract into this warp's smem CSR row
    unsigned short* sw = &se[warp][0];
    #pragma unroll
    for (int c = 0; c < 4; c++) {
        unsigned u  = (c == 0) ? u0   : (c == 1) ? u1   : (c == 2) ? u2   : u3;
        unsigned w0 = (c == 0) ? a0.x : (c == 1) ? a0.y : (c == 2) ? a0.z : a0.w;
        unsigned w1 = (c == 0) ? a1.x : (c == 1) ? a1.y : (c == 2) ? a1.z : a1.w;
        unsigned w2 = (c == 0) ? a2.x : (c == 1) ? a2.y : (c == 2) ? a2.z : a2.w;
        int col = (lane * 4 + c) * 32;
        while (u) {
            int b = __ffs(u) - 1;
            u &= u - 1;
            int m = ((w0 >> b) & 1) | (((w1 >> b) & 1) << 1) | (((w2 >> b) & 1) << 2);
            sw[base++] = (unsigned short)((col + b) | (m << 12));
        }
    }
    if (lane == 31 && (tot & 1)) sw[tot] = 0;     // pad entry (exact no-op)
    int cpad = (tot + 1) & ~1;
    if (lane == 0) g_cnt[row] = cpad;

    __syncthreads();                               // ss + red + se ready
    if (tid < 32) {
        float v = red[tid];
        #pragma unroll
        for (int o = 16; o; o >>= 1) v += __shfl_xor_sync(0xFFFFFFFFu, v, o);
        if (tid == 0) shS = v;
    }
    __syncthreads();

    // ---- F: layer-0 attention, entries from smem
    float S  = shS;
    float si = ss[row];
    float a0f = ab[0], b0f = ab[1], a1f = ab[2], b1f = ab[3];
    float c0 = a0f * si, c1 = a1f * si;

    const unsigned* ep32 = reinterpret_cast<const unsigned*>(sw);
    int nit = cpad >> 1;
    float e0 = 0.0f, n0 = 0.0f, e1 = 0.0f, n1 = 0.0f, sjs = 0.0f;

    for (int k = lane; k < nit; k += 32) {
        unsigned pr = ep32[k];
        #pragma unroll
        for (int half = 0; half < 2; half++) {
            int e = (half == 0) ? (pr & 0xFFFFu) : (pr >> 16);
            int j = e & 0xFFF;
            int m = e >> 12;
            float4 t4 = tab[m];           // (lut0', lut1', M, _)
            float sj = ss[j];
            float M  = t4.z;

            float x0 = fmaf(M, fmaf(b0f, sj, c0), t4.x);
            x0 = fmaxf(x0, NEG * x0);     // lrelu commutes with log2e scale
            float v0 = ex2f(x0);
            e0 += v0; n0 = fmaf(v0, sj, n0);

            float x1 = fmaf(M, fmaf(b1f, sj, c1), t4.y);
            x1 = fmaxf(x1, NEG * x1);
            float v1 = ex2f(x1);
            e1 += v1; n1 = fmaf(v1, sj, n1);

            sjs += sj;
        }
    }

    // ---- E (moved late): stream used entries to gmem for layer 1
    {
        int nv4 = (cpad + 7) >> 3;                // uint4 vectors in use
        uint4* go = reinterpret_cast<uint4*>(&g_ent[row * MAXDEG]);
        const uint4* so = reinterpret_cast<const uint4*>(sw);
        if (lane < nv4)      go[lane]      = so[lane];
        if (lane + 32 < nv4) go[lane + 32] = so[lane + 32];
    }

    #pragma unroll
    for (int o = 16; o; o >>= 1) {
        e0  += __shfl_xor_sync(0xFFFFFFFFu, e0,  o);
        n0  += __shfl_xor_sync(0xFFFFFFFFu, n0,  o);
        e1  += __shfl_xor_sync(0xFFFFFFFFu, e1,  o);
        n1  += __shfl_xor_sync(0xFFFFFFFFu, n1,  o);
        sjs += __shfl_xor_sync(0xFFFFFFFFu, sjs, o);
    }
    if (lane == 0) {
        float fc = (float)cpad;
        float r0 = (S + n0 - sjs) / ((float)NN + e0 - fc);
        float r1 = (S + n1 - sjs) / ((float)NN + e1 - fc);
        g_s1[row] = 0.5f * (r0 + r1);
    }
}

// ------------------------------------- layer-1 attention (entries L2-warm)
__global__ void __launch_bounds__(1024) k_pass1(const float* __restrict__ edge_emb,
                                                const float* __restrict__ att_w,
                                                float* __restrict__ out) {
    __shared__ float  ss[NN];
    __shared__ float4 tab[8];
    __shared__ float  ab[4];
    __shared__ float  red[32];
    __shared__ float  shS;

    int tid = threadIdx.x, warp = tid >> 5, lane = tid & 31;
    int row = blockIdx.x * 32 + warp;

    int cnt = g_cnt[row];
    const unsigned* __restrict__ ep32 =
        reinterpret_cast<const unsigned*>(&g_ent[row * MAXDEG]);
    unsigned pr[6];
    #pragma unroll
    for (int q = 0; q < 6; q++) pr[q] = ep32[lane + q * 32];   // MLP=6

    float4 sv = __ldcg(reinterpret_cast<const float4*>(g_s1) + tid);
    reinterpret_cast<float4*>(ss)[tid] = sv;
    float part = (sv.x + sv.y) + (sv.z + sv.w);
    #pragma unroll
    for (int o = 16; o; o >>= 1) part += __shfl_xor_sync(0xFFFFFFFFu, part, o);
    if (lane == 0) red[warp] = part;
    compute_consts(1, tid, edge_emb, att_w, reinterpret_cast<float*>(tab), ab);
    __syncthreads();

    if (tid < 32) {
        float v = red[tid];
        #pragma unroll
        for (int o = 16; o; o >>= 1) v += __shfl_xor_sync(0xFFFFFFFFu, v, o);
        if (tid == 0) shS = v;
    }
    __syncthreads();

    float S  = shS;
    float si = ss[row];
    float a0f = ab[0], b0f = ab[1], a1f = ab[2], b1f = ab[3];
    float c0 = a0f * si, c1 = a1f * si;

    int nit = cnt >> 1;
    float e0 = 0.0f, n0 = 0.0f, e1 = 0.0f, n1 = 0.0f, sjs = 0.0f;

    #pragma unroll
    for (int q = 0; q < 6; q++) {
        if (lane + q * 32 < nit) {
            unsigned prq = pr[q];
            #pragma unroll
            for (int half = 0; half < 2; half++) {
                int e = (half == 0) ? (prq & 0xFFFFu) : (prq >> 16);
                int j = e & 0xFFF;
                int m = e >> 12;
                float4 t4 = tab[m];
                float sj = ss[j];
                float M  = t4.z;

                float x0 = fmaf(M, fmaf(b0f, sj, c0), t4.x);
                x0 = fmaxf(x0, NEG * x0);
                float v0 = ex2f(x0);
                e0 += v0; n0 = fmaf(v0, sj, n0);

                float x1 = fmaf(M, fmaf(b1f, sj, c1), t4.y);
                x1 = fmaxf(x1, NEG * x1);
                float v1 = ex2f(x1);
                e1 += v1; n1 = fmaf(v1, sj, n1);

                sjs += sj;
            }
        }
    }

    #pragma unroll
    for (int o = 16; o; o >>= 1) {
        e0  += __shfl_xor_sync(0xFFFFFFFFu, e0,  o);
        n0  += __shfl_xor_sync(0xFFFFFFFFu, n0,  o);
        e1  += __shfl_xor_sync(0xFFFFFFFFu, e1,  o);
        n1  += __shfl_xor_sync(0xFFFFFFFFu, n1,  o);
        sjs += __shfl_xor_sync(0xFFFFFFFFu, sjs, o);
    }
    if (lane == 0) {
        float fc = (float)cnt;
        float r0 = (S + n0 - sjs) / ((float)NN + e0 - fc);
        float r1 = (S + n1 - sjs) / ((float)NN + e1 - fc);
        out[row] = 0.5f * (r0 + r1);
    }
}

// ---------------------------------------------------------------- launch
extern "C" void kernel_launch(void* const* d_in, const int* in_sizes, int n_in,
                              void* d_out, int out_size) {
    const float* inputs     = (const float*)d_in[0];
    const float* lin_w      = (const float*)d_in[1];
    const float* lin_b      = (const float*)d_in[2];
    const float* edge_emb   = (const float*)d_in[3];
    const float* att_w      = (const float*)d_in[4];
    const int*   edge_lists = (const int*)  d_in[5];
    float* out = (float*)d_out;

    k_prep <<<PREP_BLKS, 256>>>(edge_lists, inputs, lin_w, lin_b);
    k_pass0<<<PASS_BLKS, 1024>>>(edge_emb, att_w);
    k_pass1<<<PASS_BLKS, 1024>>>(edge_emb, att_w, out);
}

// round 15
// speedup vs baseline: 1.4627x; 1.0731x over previous
#include <cuda_runtime.h>

#define NN 4096
#define TT 3
#define DD 20
#define EE 131072      // 2^17
#define ATT_DIM 128
#define HEADS 2
#define LAYERS 2
#define WPR 128        // 32-bit words per bitmap row (4096/32)
#define NEG 0.2f
#define MAXDEG 384     // mean degree ~191; max-degree ~254 across rows
#define L2E 1.4426950408889634f

#define SCAT_BLKS (TT * EE * 2 / 256)          // 3072: one directed half-edge/thread
#define SCORE_BLKS 512                         // 4096 rows / 8 warps
#define PREP_BLKS (SCAT_BLKS + SCORE_BLKS)
#define PASS_BLKS 128                          // 32 rows/block, single wave

// ---- device scratch (static, allocation-free) ----
// 3 separate bitmaps (6MB). Start zeroed (.bss); k_pass0 re-zeroes after
// reading -> invariant holds across graph replays.
__device__ __align__(16) unsigned g_bm[TT][NN * WPR];          // 6MB
__device__ __align__(16) unsigned short g_ent[NN * MAXDEG];    // j | (m<<12)
__device__ int    g_cnt[NN];                                   // even (padded)
__device__ __align__(16) float g_s0[NN];
__device__ __align__(16) float g_s1[NN];

__device__ __forceinline__ float ex2f(float x) {
    float r;
    asm("ex2.approx.ftz.f32 %0, %1;" : "=f"(r) : "f"(x));
    return r;
}
__device__ __forceinline__ void red_or(unsigned* p, unsigned v) {
    asm volatile("red.global.or.b32 [%0], %1;" :: "l"(p), "r"(v) : "memory");
}

// per-layer constants from raw inputs. tabf: [m][4]=(lut_h0',lut_h1',M,_)
__device__ __forceinline__ void compute_consts(int layer, int tid,
                                               const float* __restrict__ edge_emb,
                                               const float* __restrict__ att_w,
                                               float* tabf, float* ab) {
    if (tid < HEADS) {
        int h = tid;
        const float* w = att_w + (layer * HEADS + h) * (DD + 2);
        float et[TT];
        #pragma unroll
        for (int t = 0; t < TT; t++) {
            float acc = 0.0f;
            #pragma unroll
            for (int d = 0; d < DD; d++) acc += edge_emb[t * DD + d] * w[1 + d];
            et[t] = acc * L2E;
        }
        ab[h * 2 + 0] = w[0] * L2E;
        ab[h * 2 + 1] = w[DD + 1] * L2E;
        #pragma unroll
        for (int m = 0; m < 8; m++) {
            float B = 0.0f;
            #pragma unroll
            for (int t = 0; t < TT; t++) if ((m >> t) & 1) B += et[t];
            tabf[m * 4 + h] = B;
        }
    } else if (tid == 2) {
        #pragma unroll
        for (int m = 0; m < 8; m++) tabf[m * 4 + 2] = (float)__popc((unsigned)m);
    }
}

// ----------------------- fused: edge scatter + initial scores
__global__ void __launch_bounds__(256) k_prep(const int* __restrict__ el,
                                              const float* __restrict__ inputs,
                                              const float* __restrict__ lw,
                                              const float* __restrict__ lb) {
    int bid = blockIdx.x, tid = threadIdx.x;

    if (bid < SCAT_BLKS) {
        // ---- edge scatter: one DIRECTED half-edge per thread (max concurrency)
        int i   = bid * 256 + tid;         // i < 2*TT*EE
        int dir = i & 1;
        int eid = i >> 1;                  // eid < TT*EE
        int t   = eid >> 17;               // EE = 2^17
        int e   = eid & (EE - 1);
        int s = el[(t * 2 + 0) * EE + e];
        int g = el[(t * 2 + 1) * EE + e];
        int from = dir ? g : s;
        int to   = dir ? s : g;
        red_or(&g_bm[t][from * WPR + (to >> 5)], 1u << (to & 31));
    } else {
        // ---- initial linear scores: one row per warp, 8 warps
        int warp = tid >> 5, lane = tid & 31;
        int row  = (bid - SCAT_BLKS) * 8 + warp;
        float4 v = reinterpret_cast<const float4*>(inputs + row * ATT_DIM)[lane];
        float4 w = reinterpret_cast<const float4*>(lw)[lane];
        float acc = v.x * w.x + v.y * w.y + v.z * w.z + v.w * w.w;
        #pragma unroll
        for (int o = 16; o; o >>= 1) acc += __shfl_xor_sync(0xFFFFFFFFu, acc, o);
        if (lane == 0) g_s0[row] = acc + lb[0];
    }
}

// ---------------- fused: CSR build (own 32 rows) + attention layer 0
// 128 blocks x 1024 threads; warp w owns row blk*32+w; lane owns 4 words/type.
__global__ void __launch_bounds__(1024) k_pass0(const float* __restrict__ edge_emb,
                                                const float* __restrict__ att_w) {
    __shared__ float  ss[NN];                                // 16KB scores
    __shared__ __align__(16) unsigned short se[32][MAXDEG];  // 24KB CSR rows
    __shared__ float4 tab[8];
    __shared__ float  ab[4];
    __shared__ float  red[32];
    __shared__ float  shS;

    int tid = threadIdx.x, warp = tid >> 5, lane = tid & 31;
    int row = blockIdx.x * 32 + warp;

    // ---- A: read this row's bitmap words (uint4 per type), zero-restore
    uint4* b0p = reinterpret_cast<uint4*>(&g_bm[0][0]) + row * 32 + lane;
    uint4* b1p = reinterpret_cast<uint4*>(&g_bm[1][0]) + row * 32 + lane;
    uint4* b2p = reinterpret_cast<uint4*>(&g_bm[2][0]) + row * 32 + lane;
    uint4 a0 = *b0p, a1 = *b1p, a2 = *b2p;

    // ---- B: stage scores + S partials + constants (overlaps bitmap waits)
    float4 sv = __ldcg(reinterpret_cast<const float4*>(g_s0) + tid);
    reinterpret_cast<float4*>(ss)[tid] = sv;
    float part = (sv.x + sv.y) + (sv.z + sv.w);
    #pragma unroll
    for (int o = 16; o; o >>= 1) part += __shfl_xor_sync(0xFFFFFFFFu, part, o);
    if (lane == 0) red[warp] = part;
    compute_consts(0, tid, edge_emb, att_w, reinterpret_cast<float*>(tab), ab);

    uint4 z = make_uint4(0u, 0u, 0u, 0u);
    *b0p = z; *b1p = z; *b2p = z;                 // restore zero invariant

    // ---- C: per-lane counts + warp scan
    unsigned u0 = a0.x | a1.x | a2.x;
    unsigned u1 = a0.y | a1.y | a2.y;
    unsigned u2 = a0.z | a1.z | a2.z;
    unsigned u3 = a0.w | a1.w | a2.w;
    int cnt = __popc(u0) + __popc(u1) + __popc(u2) + __popc(u3);

    int inc = cnt;
    #pragma unroll
    for (int o = 1; o < 32; o <<= 1) {
        int n = __shfl_up_sync(0xFFFFFFFFu, inc, o);
        if (lane >= o) inc += n;
    }
    int base = inc - cnt;
    int tot  = __shfl_sync(0xFFFFFFFFu, inc, 31);

    // ---- D: extract into this warp's smem CSR row
    unsigned short* sw = &se[warp][0];
    #pragma unroll
    for (int c = 0; c < 4; c++) {
        unsigned u  = (c == 0) ? u0   : (c == 1) ? u1   : (c == 2) ? u2   : u3;
        unsigned w0 = (c == 0) ? a0.x : (c == 1) ? a0.y : (c == 2) ? a0.z : a0.w;
        unsigned w1 = (c == 0) ? a1.x : (c == 1) ? a1.y : (c == 2) ? a1.z : a1.w;
        unsigned w2 = (c == 0) ? a2.x : (c == 1) ? a2.y : (c == 2) ? a2.z : a2.w;
        int col = (lane * 4 + c) * 32;
        while (u) {
            int b = __ffs(u) - 1;
            u &= u - 1;
            int m = ((w0 >> b) & 1) | (((w1 >> b) & 1) << 1) | (((w2 >> b) & 1) << 2);
            sw[base++] = (unsigned short)((col + b) | (m << 12));
        }
    }
    if (lane == 31 && (tot & 1)) sw[tot] = 0;     // pad entry (exact no-op)
    int cpad = (tot + 1) & ~1;
    if (lane == 0) g_cnt[row] = cpad;
    __syncwarp();

    // ---- E: stream entries to gmem for layer 1 (48 uint4, coalesced; early,
    // fire-and-forget — drains under the attention loop. Do NOT move late.)
    {
        uint4* go = reinterpret_cast<uint4*>(&g_ent[row * MAXDEG]);
        const uint4* so = reinterpret_cast<const uint4*>(sw);
        go[lane] = so[lane];
        if (lane < 16) go[lane + 32] = so[lane + 32];
    }

    __syncthreads();                               // ss + red + se ready
    if (tid < 32) {
        float v = red[tid];
        #pragma unroll
        for (int o = 16; o; o >>= 1) v += __shfl_xor_sync(0xFFFFFFFFu, v, o);
        if (tid == 0) shS = v;
    }
    __syncthreads();

    // ---- F: layer-0 attention, entries from smem
    float S  = shS;
    float si = ss[row];
    float a0f = ab[0], b0f = ab[1], a1f = ab[2], b1f = ab[3];
    float c0 = a0f * si, c1 = a1f * si;

    const unsigned* ep32 = reinterpret_cast<const unsigned*>(sw);
    int nit = cpad >> 1;
    float e0 = 0.0f, n0 = 0.0f, e1 = 0.0f, n1 = 0.0f, sjs = 0.0f;

    for (int k = lane; k < nit; k += 32) {
        unsigned pr = ep32[k];
        #pragma unroll
        for (int half = 0; half < 2; half++) {
            int e = (half == 0) ? (pr & 0xFFFFu) : (pr >> 16);
            int j = e & 0xFFF;
            int m = e >> 12;
            float4 t4 = tab[m];           // (lut0', lut1', M, _)
            float sj = ss[j];
            float M  = t4.z;

            float x0 = fmaf(M, fmaf(b0f, sj, c0), t4.x);
            x0 = fmaxf(x0, NEG * x0);     // lrelu commutes with log2e scale
            float v0 = ex2f(x0);
            e0 += v0; n0 = fmaf(v0, sj, n0);

            float x1 = fmaf(M, fmaf(b1f, sj, c1), t4.y);
            x1 = fmaxf(x1, NEG * x1);
            float v1 = ex2f(x1);
            e1 += v1; n1 = fmaf(v1, sj, n1);

            sjs += sj;
        }
    }

    #pragma unroll
    for (int o = 16; o; o >>= 1) {
        e0  += __shfl_xor_sync(0xFFFFFFFFu, e0,  o);
        n0  += __shfl_xor_sync(0xFFFFFFFFu, n0,  o);
        e1  += __shfl_xor_sync(0xFFFFFFFFu, e1,  o);
        n1  += __shfl_xor_sync(0xFFFFFFFFu, n1,  o);
        sjs += __shfl_xor_sync(0xFFFFFFFFu, sjs, o);
    }
    if (lane == 0) {
        float fc = (float)cpad;
        float r0 = (S + n0 - sjs) / ((float)NN + e0 - fc);
        float r1 = (S + n1 - sjs) / ((float)NN + e1 - fc);
        g_s1[row] = 0.5f * (r0 + r1);
    }
}

// ------------------------------------- layer-1 attention (entries L2-warm)
__global__ void __launch_bounds__(1024) k_pass1(const float* __restrict__ edge_emb,
                                                const float* __restrict__ att_w,
                                                float* __restrict__ out) {
    __shared__ float  ss[NN];
    __shared__ float4 tab[8];
    __shared__ float  ab[4];
    __shared__ float  red[32];
    __shared__ float  shS;

    int tid = threadIdx.x, warp = tid >> 5, lane = tid & 31;
    int row = blockIdx.x * 32 + warp;

    // constants from raw inputs (issue early, overlaps entry prefetch)
    compute_consts(1, tid, edge_emb, att_w, reinterpret_cast<float*>(tab), ab);

    int cnt = g_cnt[row];
    const unsigned* __restrict__ ep32 =
        reinterpret_cast<const unsigned*>(&g_ent[row * MAXDEG]);
    unsigned pr[6];
    #pragma unroll
    for (int q = 0; q < 6; q++) pr[q] = ep32[lane + q * 32];   // MLP=6

    float4 sv = __ldcg(reinterpret_cast<const float4*>(g_s1) + tid);
    reinterpret_cast<float4*>(ss)[tid] = sv;
    float part = (sv.x + sv.y) + (sv.z + sv.w);
    #pragma unroll
    for (int o = 16; o; o >>= 1) part += __shfl_xor_sync(0xFFFFFFFFu, part, o);
    if (lane == 0) red[warp] = part;
    __syncthreads();

    if (tid < 32) {
        float v = red[tid];
        #pragma unroll
        for (int o = 16; o; o >>= 1) v += __shfl_xor_sync(0xFFFFFFFFu, v, o);
        if (tid == 0) shS = v;
    }
    __syncthreads();

    float S  = shS;
    float si = ss[row];
    float a0f = ab[0], b0f = ab[1], a1f = ab[2], b1f = ab[3];
    float c0 = a0f * si, c1 = a1f * si;

    int nit = cnt >> 1;
    float e0 = 0.0f, n0 = 0.0f, e1 = 0.0f, n1 = 0.0f, sjs = 0.0f;

    #pragma unroll
    for (int q = 0; q < 6; q++) {
        if (lane + q * 32 < nit) {
            unsigned prq = pr[q];
            #pragma unroll
            for (int half = 0; half < 2; half++) {
                int e = (half == 0) ? (prq & 0xFFFFu) : (prq >> 16);
                int j = e & 0xFFF;
                int m = e >> 12;
                float4 t4 = tab[m];
                float sj = ss[j];
                float M  = t4.z;

                float x0 = fmaf(M, fmaf(b0f, sj, c0), t4.x);
                x0 = fmaxf(x0, NEG * x0);
                float v0 = ex2f(x0);
                e0 += v0; n0 = fmaf(v0, sj, n0);

                float x1 = fmaf(M, fmaf(b1f, sj, c1), t4.y);
                x1 = fmaxf(x1, NEG * x1);
                float v1 = ex2f(x1);
                e1 += v1; n1 = fmaf(v1, sj, n1);

                sjs += sj;
            }
        }
    }

    #pragma unroll
    for (int o = 16; o; o >>= 1) {
        e0  += __shfl_xor_sync(0xFFFFFFFFu, e0,  o);
        n0  += __shfl_xor_sync(0xFFFFFFFFu, n0,  o);
        e1  += __shfl_xor_sync(0xFFFFFFFFu, e1,  o);
        n1  += __shfl_xor_sync(0xFFFFFFFFu, n1,  o);
        sjs += __shfl_xor_sync(0xFFFFFFFFu, sjs, o);
    }
    if (lane == 0) {
        float fc = (float)cnt;
        float r0 = (S + n0 - sjs) / ((float)NN + e0 - fc);
        float r1 = (S + n1 - sjs) / ((float)NN + e1 - fc);
        out[row] = 0.5f * (r0 + r1);
    }
}

// ---------------------------------------------------------------- launch
extern "C" void kernel_launch(void* const* d_in, const int* in_sizes, int n_in,
                              void* d_out, int out_size) {
    const float* inputs     = (const float*)d_in[0];
    const float* lin_w      = (const float*)d_in[1];
    const float* lin_b      = (const float*)d_in[2];
    const float* edge_emb   = (const float*)d_in[3];
    const float* att_w      = (const float*)d_in[4];
    const int*   edge_lists = (const int*)  d_in[5];
    float* out = (float*)d_out;

    k_prep <<<PREP_BLKS, 256>>>(edge_lists, inputs, lin_w, lin_b);
    k_pass0<<<PASS_BLKS, 1024>>>(edge_emb, att_w);
    k_pass1<<<PASS_BLKS, 1024>>>(edge_emb, att_w, out);
}

// round 16
// speedup vs baseline: 1.4672x; 1.0031x over previous
#include <cuda_runtime.h>

#define NN 4096
#define TT 3
#define DD 20
#define EE 131072      // 2^17
#define ATT_DIM 128
#define HEADS 2
#define LAYERS 2
#define WPR 128        // 32-bit words per bitmap row (4096/32)
#define NEG 0.2f
#define MAXDEG 384     // mean degree ~191; max-degree ~254 across rows
#define L2E 1.4426950408889634f

#define SCAT_BLKS (TT * EE / 256)              // 1536: one edge/thread, 2 REDs
#define SCORE_BLKS 512                         // 4096 rows / 8 warps
#define PREP_BLKS (SCAT_BLKS + SCORE_BLKS)
#define PASS_BLKS 128                          // 32 rows/block, single wave

// ---- device scratch (static, allocation-free) ----
// 3 separate bitmaps (6MB). Start zeroed (.bss); k_pass0 re-zeroes after
// reading -> invariant holds across graph replays.
__device__ __align__(16) unsigned g_bm[TT][NN * WPR];          // 6MB
__device__ __align__(16) unsigned short g_ent[NN * MAXDEG];    // j | (m<<12)
__device__ int    g_cnt[NN];                                   // even (padded)
__device__ __align__(16) float g_s0[NN];
__device__ __align__(16) float g_s1[NN];

__device__ __forceinline__ float ex2f(float x) {
    float r;
    asm("ex2.approx.ftz.f32 %0, %1;" : "=f"(r) : "f"(x));
    return r;
}
__device__ __forceinline__ void red_or(unsigned* p, unsigned v) {
    asm volatile("red.global.or.b32 [%0], %1;" :: "l"(p), "r"(v) : "memory");
}

// per-layer constants from raw inputs. tabf: [m][4]=(lut_h0',lut_h1',M,_)
__device__ __forceinline__ void compute_consts(int layer, int tid,
                                               const float* __restrict__ edge_emb,
                                               const float* __restrict__ att_w,
                                               float* tabf, float* ab) {
    if (tid < HEADS) {
        int h = tid;
        const float* w = att_w + (layer * HEADS + h) * (DD + 2);
        float et[TT];
        #pragma unroll
        for (int t = 0; t < TT; t++) {
            float acc = 0.0f;
            #pragma unroll
            for (int d = 0; d < DD; d++) acc += edge_emb[t * DD + d] * w[1 + d];
            et[t] = acc * L2E;
        }
        ab[h * 2 + 0] = w[0] * L2E;
        ab[h * 2 + 1] = w[DD + 1] * L2E;
        #pragma unroll
        for (int m = 0; m < 8; m++) {
            float B = 0.0f;
            #pragma unroll
            for (int t = 0; t < TT; t++) if ((m >> t) & 1) B += et[t];
            tabf[m * 4 + h] = B;
        }
    } else if (tid == 2) {
        #pragma unroll
        for (int m = 0; m < 8; m++) tabf[m * 4 + 2] = (float)__popc((unsigned)m);
    }
}

// ----------------------- fused: edge scatter + initial scores
__global__ void __launch_bounds__(256) k_prep(const int* __restrict__ el,
                                              const float* __restrict__ inputs,
                                              const float* __restrict__ lw,
                                              const float* __restrict__ lb) {
    int bid = blockIdx.x, tid = threadIdx.x;

    if (bid < SCAT_BLKS) {
        // ---- edge scatter: one edge per thread, both directions (R8 config:
        // edge list read once; 2 independent fire-and-forget REDs)
        int i = bid * 256 + tid;           // i < TT*EE
        int t = i >> 17;                   // EE = 2^17
        int e = i & (EE - 1);
        int s = el[(t * 2 + 0) * EE + e];
        int g = el[(t * 2 + 1) * EE + e];
        unsigned* bm = &g_bm[t][0];
        red_or(&bm[s * WPR + (g >> 5)], 1u << (g & 31));
        red_or(&bm[g * WPR + (s >> 5)], 1u << (s & 31));
    } else {
        // ---- initial linear scores: one row per warp, 8 warps
        int warp = tid >> 5, lane = tid & 31;
        int row  = (bid - SCAT_BLKS) * 8 + warp;
        float4 v = reinterpret_cast<const float4*>(inputs + row * ATT_DIM)[lane];
        float4 w = reinterpret_cast<const float4*>(lw)[lane];
        float acc = v.x * w.x + v.y * w.y + v.z * w.z + v.w * w.w;
        #pragma unroll
        for (int o = 16; o; o >>= 1) acc += __shfl_xor_sync(0xFFFFFFFFu, acc, o);
        if (lane == 0) g_s0[row] = acc + lb[0];
    }
}

// ---------------- fused: CSR build (own 32 rows) + attention layer 0
// 128 blocks x 1024 threads; warp w owns row blk*32+w; lane owns 4 words/type.
__global__ void __launch_bounds__(1024) k_pass0(const float* __restrict__ edge_emb,
                                                const float* __restrict__ att_w) {
    __shared__ float  ss[NN];                                // 16KB scores
    __shared__ __align__(16) unsigned short se[32][MAXDEG];  // 24KB CSR rows
    __shared__ float4 tab[8];
    __shared__ float  ab[4];
    __shared__ float  red[32];
    __shared__ float  shS;

    int tid = threadIdx.x, warp = tid >> 5, lane = tid & 31;
    int row = blockIdx.x * 32 + warp;

    // ---- A: read this row's bitmap words (uint4 per type), zero-restore
    uint4* b0p = reinterpret_cast<uint4*>(&g_bm[0][0]) + row * 32 + lane;
    uint4* b1p = reinterpret_cast<uint4*>(&g_bm[1][0]) + row * 32 + lane;
    uint4* b2p = reinterpret_cast<uint4*>(&g_bm[2][0]) + row * 32 + lane;
    uint4 a0 = *b0p, a1 = *b1p, a2 = *b2p;

    // ---- B: stage scores + S partials + constants (overlaps bitmap waits)
    float4 sv = __ldcg(reinterpret_cast<const float4*>(g_s0) + tid);
    reinterpret_cast<float4*>(ss)[tid] = sv;
    float part = (sv.x + sv.y) + (sv.z + sv.w);
    #pragma unroll
    for (int o = 16; o; o >>= 1) part += __shfl_xor_sync(0xFFFFFFFFu, part, o);
    if (lane == 0) red[warp] = part;
    compute_consts(0, tid, edge_emb, att_w, reinterpret_cast<float*>(tab), ab);

    uint4 z = make_uint4(0u, 0u, 0u, 0u);
    *b0p = z; *b1p = z; *b2p = z;                 // restore zero invariant

    // ---- C: per-lane counts + warp scan
    unsigned u0 = a0.x | a1.x | a2.x;
    unsigned u1 = a0.y | a1.y | a2.y;
    unsigned u2 = a0.z | a1.z | a2.z;
    unsigned u3 = a0.w | a1.w | a2.w;
    int cnt = __popc(u0) + __popc(u1) + __popc(u2) + __popc(u3);

    int inc = cnt;
    #pragma unroll
    for (int o = 1; o < 32; o <<= 1) {
        int n = __shfl_up_sync(0xFFFFFFFFu, inc, o);
        if (lane >= o) inc += n;
    }
    int base = inc - cnt;
    int tot  = __shfl_sync(0xFFFFFFFFu, inc, 31);

    // ---- D: extract into this warp's smem CSR row
    unsigned short* sw = &se[warp][0];
    #pragma unroll
    for (int c = 0; c < 4; c++) {
        unsigned u  = (c == 0) ? u0   : (c == 1) ? u1   : (c == 2) ? u2   : u3;
        unsigned w0 = (c == 0) ? a0.x : (c == 1) ? a0.y : (c == 2) ? a0.z : a0.w;
        unsigned w1 = (c == 0) ? a1.x : (c == 1) ? a1.y : (c == 2) ? a1.z : a1.w;
        unsigned w2 = (c == 0) ? a2.x : (c == 1) ? a2.y : (c == 2) ? a2.z : a2.w;
        int col = (lane * 4 + c) * 32;
        while (u) {
            int b = __ffs(u) - 1;
            u &= u - 1;
            int m = ((w0 >> b) & 1) | (((w1 >> b) & 1) << 1) | (((w2 >> b) & 1) << 2);
            sw[base++] = (unsigned short)((col + b) | (m << 12));
        }
    }
    if (lane == 31 && (tot & 1)) sw[tot] = 0;     // pad entry (exact no-op)
    int cpad = (tot + 1) & ~1;
    if (lane == 0) g_cnt[row] = cpad;
    __syncwarp();

    // ---- E: stream entries to gmem for layer 1 (48 uint4, coalesced; early,
    // fire-and-forget — drains under the attention loop. Do NOT move late.)
    {
        uint4* go = reinterpret_cast<uint4*>(&g_ent[row * MAXDEG]);
        const uint4* so = reinterpret_cast<const uint4*>(sw);
        go[lane] = so[lane];
        if (lane < 16) go[lane + 32] = so[lane + 32];
    }

    __syncthreads();                               // ss + red + se ready
    if (tid < 32) {
        float v = red[tid];
        #pragma unroll
        for (int o = 16; o; o >>= 1) v += __shfl_xor_sync(0xFFFFFFFFu, v, o);
        if (tid == 0) shS = v;
    }
    __syncthreads();

    // ---- F: layer-0 attention, entries from smem
    float S  = shS;
    float si = ss[row];
    float a0f = ab[0], b0f = ab[1], a1f = ab[2], b1f = ab[3];
    float c0 = a0f * si, c1 = a1f * si;

    const unsigned* ep32 = reinterpret_cast<const unsigned*>(sw);
    int nit = cpad >> 1;
    float e0 = 0.0f, n0 = 0.0f, e1 = 0.0f, n1 = 0.0f, sjs = 0.0f;

    for (int k = lane; k < nit; k += 32) {
        unsigned pr = ep32[k];
        #pragma unroll
        for (int half = 0; half < 2; half++) {
            int e = (half == 0) ? (pr & 0xFFFFu) : (pr >> 16);
            int j = e & 0xFFF;
            int m = e >> 12;
            float4 t4 = tab[m];           // (lut0', lut1', M, _)
            float sj = ss[j];
            float M  = t4.z;

            float x0 = fmaf(M, fmaf(b0f, sj, c0), t4.x);
            x0 = fmaxf(x0, NEG * x0);     // lrelu commutes with log2e scale
            float v0 = ex2f(x0);
            e0 += v0; n0 = fmaf(v0, sj, n0);

            float x1 = fmaf(M, fmaf(b1f, sj, c1), t4.y);
            x1 = fmaxf(x1, NEG * x1);
            float v1 = ex2f(x1);
            e1 += v1; n1 = fmaf(v1, sj, n1);

            sjs += sj;
        }
    }

    #pragma unroll
    for (int o = 16; o; o >>= 1) {
        e0  += __shfl_xor_sync(0xFFFFFFFFu, e0,  o);
        n0  += __shfl_xor_sync(0xFFFFFFFFu, n0,  o);
        e1  += __shfl_xor_sync(0xFFFFFFFFu, e1,  o);
        n1  += __shfl_xor_sync(0xFFFFFFFFu, n1,  o);
        sjs += __shfl_xor_sync(0xFFFFFFFFu, sjs, o);
    }
    if (lane == 0) {
        float fc = (float)cpad;
        float r0 = (S + n0 - sjs) / ((float)NN + e0 - fc);
        float r1 = (S + n1 - sjs) / ((float)NN + e1 - fc);
        g_s1[row] = 0.5f * (r0 + r1);
    }
}

// ------------------------------------- layer-1 attention (entries L2-warm)
__global__ void __launch_bounds__(1024) k_pass1(const float* __restrict__ edge_emb,
                                                const float* __restrict__ att_w,
                                                float* __restrict__ out) {
    __shared__ float  ss[NN];
    __shared__ float4 tab[8];
    __shared__ float  ab[4];
    __shared__ float  red[32];
    __shared__ float  shS;

    int tid = threadIdx.x, warp = tid >> 5, lane = tid & 31;
    int row = blockIdx.x * 32 + warp;

    // constants from raw inputs (issue early, overlaps entry prefetch)
    compute_consts(1, tid, edge_emb, att_w, reinterpret_cast<float*>(tab), ab);

    int cnt = g_cnt[row];
    const unsigned* __restrict__ ep32 =
        reinterpret_cast<const unsigned*>(&g_ent[row * MAXDEG]);
    unsigned pr[6];
    #pragma unroll
    for (int q = 0; q < 6; q++) pr[q] = ep32[lane + q * 32];   // MLP=6

    float4 sv = __ldcg(reinterpret_cast<const float4*>(g_s1) + tid);
    reinterpret_cast<float4*>(ss)[tid] = sv;
    float part = (sv.x + sv.y) + (sv.z + sv.w);
    #pragma unroll
    for (int o = 16; o; o >>= 1) part += __shfl_xor_sync(0xFFFFFFFFu, part, o);
    if (lane == 0) red[warp] = part;
    __syncthreads();

    if (tid < 32) {
        float v = red[tid];
        #pragma unroll
        for (int o = 16; o; o >>= 1) v += __shfl_xor_sync(0xFFFFFFFFu, v, o);
        if (tid == 0) shS = v;
    }
    __syncthreads();

    float S  = shS;
    float si = ss[row];
    float a0f = ab[0], b0f = ab[1], a1f = ab[2], b1f = ab[3];
    float c0 = a0f * si, c1 = a1f * si;

    int nit = cnt >> 1;
    float e0 = 0.0f, n0 = 0.0f, e1 = 0.0f, n1 = 0.0f, sjs = 0.0f;

    #pragma unroll
    for (int q = 0; q < 6; q++) {
        if (lane + q * 32 < nit) {
            unsigned prq = pr[q];
            #pragma unroll
            for (int half = 0; half < 2; half++) {
                int e = (half == 0) ? (prq & 0xFFFFu) : (prq >> 16);
                int j = e & 0xFFF;
                int m = e >> 12;
                float4 t4 = tab[m];
                float sj = ss[j];
                float M  = t4.z;

                float x0 = fmaf(M, fmaf(b0f, sj, c0), t4.x);
                x0 = fmaxf(x0, NEG * x0);
                float v0 = ex2f(x0);
                e0 += v0; n0 = fmaf(v0, sj, n0);

                float x1 = fmaf(M, fmaf(b1f, sj, c1), t4.y);
                x1 = fmaxf(x1, NEG * x1);
                float v1 = ex2f(x1);
                e1 += v1; n1 = fmaf(v1, sj, n1);

                sjs += sj;
            }
        }
    }

    #pragma unroll
    for (int o = 16; o; o >>= 1) {
        e0  += __shfl_xor_sync(0xFFFFFFFFu, e0,  o);
        n0  += __shfl_xor_sync(0xFFFFFFFFu, n0,  o);
        e1  += __shfl_xor_sync(0xFFFFFFFFu, e1,  o);
        n1  += __shfl_xor_sync(0xFFFFFFFFu, n1,  o);
        sjs += __shfl_xor_sync(0xFFFFFFFFu, sjs, o);
    }
    if (lane == 0) {
        float fc = (float)cnt;
        float r0 = (S + n0 - sjs) / ((float)NN + e0 - fc);
        float r1 = (S + n1 - sjs) / ((float)NN + e1 - fc);
        out[row] = 0.5f * (r0 + r1);
    }
}

// ---------------------------------------------------------------- launch
extern "C" void kernel_launch(void* const* d_in, const int* in_sizes, int n_in,
                              void* d_out, int out_size) {
    const float* inputs     = (const float*)d_in[0];
    const float* lin_w      = (const float*)d_in[1];
    const float* lin_b      = (const float*)d_in[2];
    const float* edge_emb   = (const float*)d_in[3];
    const float* att_w      = (const float*)d_in[4];
    const int*   edge_lists = (const int*)  d_in[5];
    float* out = (float*)d_out;

    k_prep <<<PREP_BLKS, 256>>>(edge_lists, inputs, lin_w, lin_b);
    k_pass0<<<PASS_BLKS, 1024>>>(edge_emb, att_w);
    k_pass1<<<PASS_BLKS, 1024>>>(edge_emb, att_w, out);
}

// round 17
// speedup vs baseline: 1.5016x; 1.0234x over previous
#include <cuda_runtime.h>

#define NN 4096
#define TT 3
#define DD 20
#define EE 131072      // 2^17
#define ATT_DIM 128
#define HEADS 2
#define LAYERS 2
#define WPR 128        // 32-bit words per bitmap row (4096/32)
#define NEG 0.2f
#define MAXDEG 384     // mean degree ~191; max-degree ~254 across rows
#define L2E 1.4426950408889634f

#define SCAT_BLKS (TT * EE / 256)              // 1536: one edge/thread, 2 REDs
#define SCORE_BLKS 512                         // 4096 rows / 8 warps
#define PREP_BLKS (SCAT_BLKS + SCORE_BLKS)
#define PASS_BLKS 128                          // 32 rows/block, single wave

// ---- device scratch (static, allocation-free) ----
// 3 separate bitmaps (6MB). Start zeroed (.bss); k_pass0 re-zeroes after
// reading -> invariant holds across graph replays.
__device__ __align__(16) unsigned g_bm[TT][NN * WPR];          // 6MB
__device__ __align__(16) unsigned short g_ent[NN * MAXDEG];    // j | (m<<12)
__device__ int    g_cnt[NN];                                   // even (padded)
__device__ __align__(16) float g_s0[NN];
__device__ __align__(16) float g_s1[NN];

__device__ __forceinline__ float ex2f(float x) {
    float r;
    asm("ex2.approx.ftz.f32 %0, %1;" : "=f"(r) : "f"(x));
    return r;
}
__device__ __forceinline__ void red_or(unsigned* p, unsigned v) {
    asm volatile("red.global.or.b32 [%0], %1;" :: "l"(p), "r"(v) : "memory");
}
__device__ __forceinline__ void pdl_trigger() {
    asm volatile("griddepcontrol.launch_dependents;");
}
__device__ __forceinline__ void pdl_wait() {
    asm volatile("griddepcontrol.wait;" ::: "memory");
}

// per-layer constants from raw inputs. tabf: [m][4]=(lut_h0',lut_h1',M,_)
__device__ __forceinline__ void compute_consts(int layer, int tid,
                                               const float* __restrict__ edge_emb,
                                               const float* __restrict__ att_w,
                                               float* tabf, float* ab) {
    if (tid < HEADS) {
        int h = tid;
        const float* w = att_w + (layer * HEADS + h) * (DD + 2);
        float et[TT];
        #pragma unroll
        for (int t = 0; t < TT; t++) {
            float acc = 0.0f;
            #pragma unroll
            for (int d = 0; d < DD; d++) acc += edge_emb[t * DD + d] * w[1 + d];
            et[t] = acc * L2E;
        }
        ab[h * 2 + 0] = w[0] * L2E;
        ab[h * 2 + 1] = w[DD + 1] * L2E;
        #pragma unroll
        for (int m = 0; m < 8; m++) {
            float B = 0.0f;
            #pragma unroll
            for (int t = 0; t < TT; t++) if ((m >> t) & 1) B += et[t];
            tabf[m * 4 + h] = B;
        }
    } else if (tid == 2) {
        #pragma unroll
        for (int m = 0; m < 8; m++) tabf[m * 4 + 2] = (float)__popc((unsigned)m);
    }
}

// ----------------------- fused: edge scatter + initial scores
__global__ void __launch_bounds__(256) k_prep(const int* __restrict__ el,
                                              const float* __restrict__ inputs,
                                              const float* __restrict__ lw,
                                              const float* __restrict__ lb) {
    int bid = blockIdx.x, tid = threadIdx.x;

    if (bid < SCAT_BLKS) {
        // ---- edge scatter: one edge per thread, both directions
        int i = bid * 256 + tid;           // i < TT*EE
        int t = i >> 17;                   // EE = 2^17
        int e = i & (EE - 1);
        int s = el[(t * 2 + 0) * EE + e];
        int g = el[(t * 2 + 1) * EE + e];
        unsigned* bm = &g_bm[t][0];
        red_or(&bm[s * WPR + (g >> 5)], 1u << (g & 31));
        red_or(&bm[g * WPR + (s >> 5)], 1u << (s & 31));
    } else {
        // ---- initial linear scores: one row per warp, 8 warps
        int warp = tid >> 5, lane = tid & 31;
        int row  = (bid - SCAT_BLKS) * 8 + warp;
        float4 v = reinterpret_cast<const float4*>(inputs + row * ATT_DIM)[lane];
        float4 w = reinterpret_cast<const float4*>(lw)[lane];
        float acc = v.x * w.x + v.y * w.y + v.z * w.z + v.w * w.w;
        #pragma unroll
        for (int o = 16; o; o >>= 1) acc += __shfl_xor_sync(0xFFFFFFFFu, acc, o);
        if (lane == 0) g_s0[row] = acc + lb[0];
    }
}

// ---------------- fused: CSR build (own 32 rows) + attention layer 0
// 128 blocks x 1024 threads; warp w owns row blk*32+w; lane owns 4 words/type.
// Triggers pass1's launch at start (pass1 co-resides in SPARE SM capacity).
__global__ void __launch_bounds__(1024) k_pass0(const float* __restrict__ edge_emb,
                                                const float* __restrict__ att_w) {
    __shared__ float  ss[NN];                                // 16KB scores
    __shared__ __align__(16) unsigned short se[32][MAXDEG];  // 24KB CSR rows
    __shared__ float4 tab[8];
    __shared__ float  ab[4];
    __shared__ float  red[32];
    __shared__ float  shS;

    int tid = threadIdx.x, warp = tid >> 5, lane = tid & 31;
    int row = blockIdx.x * 32 + warp;

    pdl_trigger();                         // pass1 may launch into spare slots

    // ---- A: read this row's bitmap words (uint4 per type), zero-restore
    uint4* b0p = reinterpret_cast<uint4*>(&g_bm[0][0]) + row * 32 + lane;
    uint4* b1p = reinterpret_cast<uint4*>(&g_bm[1][0]) + row * 32 + lane;
    uint4* b2p = reinterpret_cast<uint4*>(&g_bm[2][0]) + row * 32 + lane;
    uint4 a0 = *b0p, a1 = *b1p, a2 = *b2p;

    // ---- B: stage scores + S partials + constants (overlaps bitmap waits)
    float4 sv = __ldcg(reinterpret_cast<const float4*>(g_s0) + tid);
    reinterpret_cast<float4*>(ss)[tid] = sv;
    float part = (sv.x + sv.y) + (sv.z + sv.w);
    #pragma unroll
    for (int o = 16; o; o >>= 1) part += __shfl_xor_sync(0xFFFFFFFFu, part, o);
    if (lane == 0) red[warp] = part;
    compute_consts(0, tid, edge_emb, att_w, reinterpret_cast<float*>(tab), ab);

    uint4 z = make_uint4(0u, 0u, 0u, 0u);
    *b0p = z; *b1p = z; *b2p = z;                 // restore zero invariant

    // ---- C: per-lane counts + warp scan
    unsigned u0 = a0.x | a1.x | a2.x;
    unsigned u1 = a0.y | a1.y | a2.y;
    unsigned u2 = a0.z | a1.z | a2.z;
    unsigned u3 = a0.w | a1.w | a2.w;
    int cnt = __popc(u0) + __popc(u1) + __popc(u2) + __popc(u3);

    int inc = cnt;
    #pragma unroll
    for (int o = 1; o < 32; o <<= 1) {
        int n = __shfl_up_sync(0xFFFFFFFFu, inc, o);
        if (lane >= o) inc += n;
    }
    int base = inc - cnt;
    int tot  = __shfl_sync(0xFFFFFFFFu, inc, 31);

    // ---- D: extract into this warp's smem CSR row
    unsigned short* sw = &se[warp][0];
    #pragma unroll
    for (int c = 0; c < 4; c++) {
        unsigned u  = (c == 0) ? u0   : (c == 1) ? u1   : (c == 2) ? u2   : u3;
        unsigned w0 = (c == 0) ? a0.x : (c == 1) ? a0.y : (c == 2) ? a0.z : a0.w;
        unsigned w1 = (c == 0) ? a1.x : (c == 1) ? a1.y : (c == 2) ? a1.z : a1.w;
        unsigned w2 = (c == 0) ? a2.x : (c == 1) ? a2.y : (c == 2) ? a2.z : a2.w;
        int col = (lane * 4 + c) * 32;
        while (u) {
            int b = __ffs(u) - 1;
            u &= u - 1;
            int m = ((w0 >> b) & 1) | (((w1 >> b) & 1) << 1) | (((w2 >> b) & 1) << 2);
            sw[base++] = (unsigned short)((col + b) | (m << 12));
        }
    }
    if (lane == 31 && (tot & 1)) sw[tot] = 0;     // pad entry (exact no-op)
    int cpad = (tot + 1) & ~1;
    if (lane == 0) g_cnt[row] = cpad;
    __syncwarp();

    // ---- E: stream entries to gmem for layer 1 (48 uint4, coalesced; early,
    // fire-and-forget — drains under the attention loop. Do NOT move late.)
    {
        uint4* go = reinterpret_cast<uint4*>(&g_ent[row * MAXDEG]);
        const uint4* so = reinterpret_cast<const uint4*>(sw);
        go[lane] = so[lane];
        if (lane < 16) go[lane + 32] = so[lane + 32];
    }

    __syncthreads();                               // ss + red + se ready
    if (tid < 32) {
        float v = red[tid];
        #pragma unroll
        for (int o = 16; o; o >>= 1) v += __shfl_xor_sync(0xFFFFFFFFu, v, o);
        if (tid == 0) shS = v;
    }
    __syncthreads();

    // ---- F: layer-0 attention, entries from smem
    float S  = shS;
    float si = ss[row];
    float a0f = ab[0], b0f = ab[1], a1f = ab[2], b1f = ab[3];
    float c0 = a0f * si, c1 = a1f * si;

    const unsigned* ep32 = reinterpret_cast<const unsigned*>(sw);
    int nit = cpad >> 1;
    float e0 = 0.0f, n0 = 0.0f, e1 = 0.0f, n1 = 0.0f, sjs = 0.0f;

    for (int k = lane; k < nit; k += 32) {
        unsigned pr = ep32[k];
        #pragma unroll
        for (int half = 0; half < 2; half++) {
            int e = (half == 0) ? (pr & 0xFFFFu) : (pr >> 16);
            int j = e & 0xFFF;
            int m = e >> 12;
            float4 t4 = tab[m];           // (lut0', lut1', M, _)
            float sj = ss[j];
            float M  = t4.z;

            float x0 = fmaf(M, fmaf(b0f, sj, c0), t4.x);
            x0 = fmaxf(x0, NEG * x0);     // lrelu commutes with log2e scale
            float v0 = ex2f(x0);
            e0 += v0; n0 = fmaf(v0, sj, n0);

            float x1 = fmaf(M, fmaf(b1f, sj, c1), t4.y);
            x1 = fmaxf(x1, NEG * x1);
            float v1 = ex2f(x1);
            e1 += v1; n1 = fmaf(v1, sj, n1);

            sjs += sj;
        }
    }

    #pragma unroll
    for (int o = 16; o; o >>= 1) {
        e0  += __shfl_xor_sync(0xFFFFFFFFu, e0,  o);
        n0  += __shfl_xor_sync(0xFFFFFFFFu, n0,  o);
        e1  += __shfl_xor_sync(0xFFFFFFFFu, e1,  o);
        n1  += __shfl_xor_sync(0xFFFFFFFFu, n1,  o);
        sjs += __shfl_xor_sync(0xFFFFFFFFu, sjs, o);
    }
    if (lane == 0) {
        float fc = (float)cpad;
        float r0 = (S + n0 - sjs) / ((float)NN + e0 - fc);
        float r1 = (S + n1 - sjs) / ((float)NN + e1 - fc);
        g_s1[row] = 0.5f * (r0 + r1);
    }
}

// ------------- layer-1 attention (PDL dependent; consts pre-wait)
__global__ void __launch_bounds__(1024) k_pass1(const float* __restrict__ edge_emb,
                                                const float* __restrict__ att_w,
                                                float* __restrict__ out) {
    __shared__ float  ss[NN];
    __shared__ float4 tab[8];
    __shared__ float  ab[4];
    __shared__ float  red[32];
    __shared__ float  shS;

    int tid = threadIdx.x, warp = tid >> 5, lane = tid & 31;
    int row = blockIdx.x * 32 + warp;

    // constants from raw inputs: safe BEFORE the wait (overlaps pass0 tail)
    compute_consts(1, tid, edge_emb, att_w, reinterpret_cast<float*>(tab), ab);

    pdl_wait();                            // pass0 flush complete

    int cnt = g_cnt[row];
    const unsigned* __restrict__ ep32 =
        reinterpret_cast<const unsigned*>(&g_ent[row * MAXDEG]);
    unsigned pr[6];
    #pragma unroll
    for (int q = 0; q < 6; q++) pr[q] = ep32[lane + q * 32];   // MLP=6

    float4 sv = __ldcg(reinterpret_cast<const float4*>(g_s1) + tid);
    reinterpret_cast<float4*>(ss)[tid] = sv;
    float part = (sv.x + sv.y) + (sv.z + sv.w);
    #pragma unroll
    for (int o = 16; o; o >>= 1) part += __shfl_xor_sync(0xFFFFFFFFu, part, o);
    if (lane == 0) red[warp] = part;
    __syncthreads();

    if (tid < 32) {
        float v = red[tid];
        #pragma unroll
        for (int o = 16; o; o >>= 1) v += __shfl_xor_sync(0xFFFFFFFFu, v, o);
        if (tid == 0) shS = v;
    }
    __syncthreads();

    float S  = shS;
    float si = ss[row];
    float a0f = ab[0], b0f = ab[1], a1f = ab[2], b1f = ab[3];
    float c0 = a0f * si, c1 = a1f * si;

    int nit = cnt >> 1;
    float e0 = 0.0f, n0 = 0.0f, e1 = 0.0f, n1 = 0.0f, sjs = 0.0f;

    #pragma unroll
    for (int q = 0; q < 6; q++) {
        if (lane + q * 32 < nit) {
            unsigned prq = pr[q];
            #pragma unroll
            for (int half = 0; half < 2; half++) {
                int e = (half == 0) ? (prq & 0xFFFFu) : (prq >> 16);
                int j = e & 0xFFF;
                int m = e >> 12;
                float4 t4 = tab[m];
                float sj = ss[j];
                float M  = t4.z;

                float x0 = fmaf(M, fmaf(b0f, sj, c0), t4.x);
                x0 = fmaxf(x0, NEG * x0);
                float v0 = ex2f(x0);
                e0 += v0; n0 = fmaf(v0, sj, n0);

                float x1 = fmaf(M, fmaf(b1f, sj, c1), t4.y);
                x1 = fmaxf(x1, NEG * x1);
                float v1 = ex2f(x1);
                e1 += v1; n1 = fmaf(v1, sj, n1);

                sjs += sj;
            }
        }
    }

    #pragma unroll
    for (int o = 16; o; o >>= 1) {
        e0  += __shfl_xor_sync(0xFFFFFFFFu, e0,  o);
        n0  += __shfl_xor_sync(0xFFFFFFFFu, n0,  o);
        e1  += __shfl_xor_sync(0xFFFFFFFFu, e1,  o);
        n1  += __shfl_xor_sync(0xFFFFFFFFu, n1,  o);
        sjs += __shfl_xor_sync(0xFFFFFFFFu, sjs, o);
    }
    if (lane == 0) {
        float fc = (float)cnt;
        float r0 = (S + n0 - sjs) / ((float)NN + e0 - fc);
        float r1 = (S + n1 - sjs) / ((float)NN + e1 - fc);
        out[row] = 0.5f * (r0 + r1);
    }
}

// ---------------------------------------------------------------- launch
extern "C" void kernel_launch(void* const* d_in, const int* in_sizes, int n_in,
                              void* d_out, int out_size) {
    const float* inputs     = (const float*)d_in[0];
    const float* lin_w      = (const float*)d_in[1];
    const float* lin_b      = (const float*)d_in[2];
    const float* edge_emb   = (const float*)d_in[3];
    const float* att_w      = (const float*)d_in[4];
    const int*   edge_lists = (const int*)  d_in[5];
    float* out = (float*)d_out;

    k_prep <<<PREP_BLKS, 256>>>(edge_lists, inputs, lin_w, lin_b);
    k_pass0<<<PASS_BLKS, 1024>>>(edge_emb, att_w);

    // pass1 is the PDL dependent of pass0 (fits in spare SM capacity)
    cudaLaunchAttribute attr[1];
    attr[0].id = cudaLaunchAttributeProgrammaticStreamSerialization;
    attr[0].val.programmaticStreamSerializationAllowed = 1;
    cudaLaunchConfig_t cfg = {};
    cfg.gridDim  = dim3(PASS_BLKS, 1, 1);
    cfg.blockDim = dim3(1024, 1, 1);
    cfg.attrs = attr;
    cfg.numAttrs = 1;
    cudaLaunchKernelEx(&cfg, k_pass1, edge_emb, att_w, out);
}